// round 6
// baseline (speedup 1.0000x reference)
#include <cuda_runtime.h>
#include <cstdint>

// Problem constants
#define B_  4
#define HC_ 32
#define WC_ 32
#define KC_ 1024
#define HF_ 128
#define WF_ 128
#define KF_ 256
#define DC_ 4

__device__ float g_anorm[B_ * HC_ * WC_];   // coarse candidate norms
__device__ float g_fnorm[B_ * HF_ * WF_];   // fine candidate norms
__device__ int   g_cm[B_ * HC_ * WC_ * 2];  // coarse result (int scratch for fine stage)

// ---------------------------------------------------------------------------
// Kernel 1: candidate squared norms (one warp per row), fully bounds-guarded.
// ---------------------------------------------------------------------------
__global__ void norms_kernel(const float* __restrict__ g1c,
                             const float* __restrict__ g1f) {
    int w    = (blockIdx.x * blockDim.x + threadIdx.x) >> 5;
    int lane = threadIdx.x & 31;
    float s = 0.f;
    if (w < B_ * HC_ * WC_) {
        const float* p = g1c + (size_t)w * KC_;
#pragma unroll
        for (int i = 0; i < KC_ / 32; i++) { float v = p[lane + i * 32]; s += v * v; }
#pragma unroll
        for (int o = 16; o; o >>= 1) s += __shfl_xor_sync(0xFFFFFFFFu, s, o);
        if (lane == 0) g_anorm[w] = s;
    } else if (w < B_ * HC_ * WC_ + B_ * HF_ * WF_) {
        int r = w - B_ * HC_ * WC_;
        const float* p = g1f + (size_t)r * KF_;
#pragma unroll
        for (int i = 0; i < KF_ / 32; i++) { float v = p[lane + i * 32]; s += v * v; }
#pragma unroll
        for (int o = 16; o; o >>= 1) s += __shfl_xor_sync(0xFFFFFFFFu, s, o);
        if (lane == 0) g_fnorm[r] = s;
    }
}

// ---------------------------------------------------------------------------
// Kernel 2: coarse match. 256 threads; 32 queries/block x 1024 candidates
// (4 tiles of 256). Thread (ty=warp, tx=lane): queries ty*4..+3 (broadcast
// reads), candidates j*32+tx (conflict-free). Scalar FMA.
// score = |a|^2 - 2 q.a  (|q|^2 constant per query -> argmin invariant)
// OUTPUT written as float32 (harness __output__ dtype hypothesis).
// ---------------------------------------------------------------------------
__global__ __launch_bounds__(256, 1)
void coarse_kernel(const float* __restrict__ A,
                   const float* __restrict__ Q,
                   float* __restrict__ out) {
    const int b   = blockIdx.y;
    const int q0  = blockIdx.x * 32;
    const int tid = threadIdx.x;
    const int ty  = tid >> 5;
    const int tx  = tid & 31;

    __shared__ float q_s[16][32];
    __shared__ float c_s[16][256];
    __shared__ float red_v[32][33];
    __shared__ int   red_i[32][33];

    const float* Ab = A + (size_t)b * (HC_ * WC_) * KC_;
    const float* Qb = Q + (size_t)b * (HC_ * WC_) * KC_;

    float minv[4]; int mini[4];
#pragma unroll
    for (int r = 0; r < 4; r++) { minv[r] = 3.402823466e38f; mini[r] = 0; }

    for (int tile = 0; tile < 4; tile++) {
        const int c0 = tile * 256;
        float acc[4][8];
#pragma unroll
        for (int r = 0; r < 4; r++)
#pragma unroll
            for (int j = 0; j < 8; j++) acc[r][j] = 0.f;

        for (int ks = 0; ks < KC_ / 16; ks++) {
            const int k0 = ks * 16;
            {   // Q tile: 32 rows x 16 k
                int row = tid >> 3, kp = (tid & 7) * 2;
                float2 v = *(const float2*)(Qb + (size_t)(q0 + row) * KC_ + k0 + kp);
                q_s[kp][row]     = v.x;
                q_s[kp + 1][row] = v.y;
            }
            {   // A tile: 256 rows x 16 k
                const float* src = Ab + (size_t)(c0 + tid) * KC_ + k0;
#pragma unroll
                for (int i = 0; i < 4; i++) {
                    float4 v = *(const float4*)(src + i * 4);
                    c_s[i * 4 + 0][tid] = v.x;
                    c_s[i * 4 + 1][tid] = v.y;
                    c_s[i * 4 + 2][tid] = v.z;
                    c_s[i * 4 + 3][tid] = v.w;
                }
            }
            __syncthreads();
#pragma unroll
            for (int k = 0; k < 16; k++) {
                float qv[4];
#pragma unroll
                for (int r = 0; r < 4; r++) qv[r] = q_s[k][ty * 4 + r];
#pragma unroll
                for (int j = 0; j < 8; j++) {
                    float cv = c_s[k][j * 32 + tx];
#pragma unroll
                    for (int r = 0; r < 4; r++) acc[r][j] += qv[r] * cv;
                }
            }
            __syncthreads();
        }
#pragma unroll
        for (int j = 0; j < 8; j++) {
            int cand = c0 + j * 32 + tx;
            float an = g_anorm[b * (HC_ * WC_) + cand];
#pragma unroll
            for (int r = 0; r < 4; r++) {
                float s = an - 2.f * acc[r][j];
                if (s < minv[r] || (s == minv[r] && cand < mini[r])) {
                    minv[r] = s; mini[r] = cand;
                }
            }
        }
    }

#pragma unroll
    for (int r = 0; r < 4; r++) {
        red_v[ty * 4 + r][tx] = minv[r];
        red_i[ty * 4 + r][tx] = mini[r];
    }
    __syncthreads();
    if (tid < 32) {
        float bv = red_v[tid][0]; int bi = red_i[tid][0];
        for (int t = 1; t < 32; t++) {
            float v = red_v[tid][t]; int i2 = red_i[tid][t];
            if (v < bv || (v == bv && i2 < bi)) { bv = v; bi = i2; }
        }
        int q = q0 + tid;
        int ro = bi >> 5, co = bi & 31;               // idx / 32, idx % 32
        out[(b * (HC_ * WC_) + q) * 2 + 0] = (float)ro;
        out[(b * (HC_ * WC_) + q) * 2 + 1] = (float)co;
        g_cm[(b * (HC_ * WC_) + q) * 2 + 0] = ro;     // int scratch for fine stage
        g_cm[(b * (HC_ * WC_) + q) * 2 + 1] = co;
    }
}

// ---------------------------------------------------------------------------
// Kernel 3: fine match. One block (128 thr) per coarse cell. Coarse map read
// from g_cm (int scratch, values clamped -> no OOB gather possible).
// 16 queries x 144 gathered candidates, two candidate passes (128 + 16).
// Duplicated candidates produce bitwise-equal scores (same dot order) ->
// smallest-index tie-break == jnp.argmin first-min. Float32 output.
// ---------------------------------------------------------------------------
__global__ __launch_bounds__(128)
void fine_kernel(const float* __restrict__ F1,
                 const float* __restrict__ FK,
                 float* __restrict__ out) {
    const int b   = blockIdx.z;
    const int ci  = blockIdx.y;
    const int cj  = blockIdx.x;
    const int tid = threadIdx.x;

    __shared__ float q_t[KF_][16];
    __shared__ float c_t[32][128];
    __shared__ int nbr_r[9], nbr_c[9];
    __shared__ float red_v[16][33];
    __shared__ int   red_i[16][33];

    if (tid < 9) {
        int di = tid / 3 - 1, dj = tid % 3 - 1;
        int ii = min(max(ci + di, 0), HC_ - 1);
        int jj = min(max(cj + dj, 0), WC_ - 1);
        const int* p = g_cm + ((b * HC_ + ii) * WC_ + jj) * 2;
        nbr_r[tid] = min(max(p[0], 0), HC_ - 1);   // clamp: fault-proof
        nbr_c[tid] = min(max(p[1], 0), WC_ - 1);
    }
    const float* QB = FK + (((size_t)(b * HF_ + ci * DC_) * WF_) + cj * DC_) * KF_;
    for (int idx = tid; idx < 16 * KF_; idx += 128) {
        int p = idx >> 8, k = idx & (KF_ - 1);
        q_t[k][p] = QB[(((p >> 2) * WF_) + (p & 3)) * KF_ + k];
    }

    const int qg = tid >> 5;
    const int cg = tid & 31;

    float minv[4]; int mini[4];
#pragma unroll
    for (int r = 0; r < 4; r++) { minv[r] = 3.402823466e38f; mini[r] = 0; }

    const float* F1b = F1 + (size_t)b * HF_ * WF_ * KF_;
    const float* fnb = g_fnorm + b * HF_ * WF_;

    __syncthreads();

    for (int pass = 0; pass < 2; pass++) {
        const int base  = pass * 128;
        const int npass = pass ? 16 : 128;
        float acc[4][4];
#pragma unroll
        for (int r = 0; r < 4; r++)
#pragma unroll
            for (int j = 0; j < 4; j++) acc[r][j] = 0.f;

        for (int ksub = 0; ksub < KF_ / 32; ksub++) {
            if (tid < npass) {
                int cand = base + tid;
                int n = cand >> 4, p2 = cand & 15;
                int rr = nbr_r[n] * DC_ + (p2 >> 2);
                int c2 = nbr_c[n] * DC_ + (p2 & 3);
                const float* src = F1b + ((size_t)rr * WF_ + c2) * KF_ + ksub * 32;
#pragma unroll
                for (int i = 0; i < 8; i++) {
                    float4 v = *(const float4*)(src + i * 4);
                    c_t[i * 4 + 0][tid] = v.x;
                    c_t[i * 4 + 1][tid] = v.y;
                    c_t[i * 4 + 2][tid] = v.z;
                    c_t[i * 4 + 3][tid] = v.w;
                }
            }
            __syncthreads();
            const int kb = ksub * 32;
#pragma unroll
            for (int kl = 0; kl < 32; kl++) {
                float qv[4];
#pragma unroll
                for (int r = 0; r < 4; r++) qv[r] = q_t[kb + kl][qg * 4 + r];
#pragma unroll
                for (int j = 0; j < 4; j++) {
                    float cv = c_t[kl][j * 32 + cg];
#pragma unroll
                    for (int r = 0; r < 4; r++) acc[r][j] += qv[r] * cv;
                }
            }
            __syncthreads();
        }
#pragma unroll
        for (int j = 0; j < 4; j++) {
            int cand = base + j * 32 + cg;
            if (cand < 144) {
                int n = cand >> 4, p2 = cand & 15;
                int rr = nbr_r[n] * DC_ + (p2 >> 2);
                int c2 = nbr_c[n] * DC_ + (p2 & 3);
                float fn = fnb[rr * WF_ + c2];
#pragma unroll
                for (int r = 0; r < 4; r++) {
                    float s = fn - 2.f * acc[r][j];
                    if (s < minv[r] || (s == minv[r] && cand < mini[r])) {
                        minv[r] = s; mini[r] = cand;
                    }
                }
            }
        }
    }

#pragma unroll
    for (int r = 0; r < 4; r++) {
        red_v[qg * 4 + r][cg] = minv[r];
        red_i[qg * 4 + r][cg] = mini[r];
    }
    __syncthreads();
    if (tid < 16) {
        float bv = red_v[tid][0]; int bi = red_i[tid][0];
        for (int t = 1; t < 32; t++) {
            float v = red_v[tid][t]; int i2 = red_i[tid][t];
            if (v < bv || (v == bv && i2 < bi)) { bv = v; bi = i2; }
        }
        int n = bi >> 4, p2 = bi & 15;
        int rr = nbr_r[n] * DC_ + (p2 >> 2);
        int c2 = nbr_c[n] * DC_ + (p2 & 3);
        int R = ci * DC_ + (tid >> 2);
        int C = cj * DC_ + (tid & 3);
        float* o = out + (((size_t)(b * HF_ + R) * WF_) + C) * 2;
        o[0] = (float)rr; o[1] = (float)c2;
    }
}

// ---------------------------------------------------------------------------
extern "C" void kernel_launch(void* const* d_in, const int* in_sizes, int n_in,
                              void* d_out, int out_size) {
    // Assumption-free binding: stable-sort inputs by (size, original index).
    // Two SMALLEST = coarse pair (g1, gk), two LARGEST = fine pair (g1, gk).
    // Correct for both dict-order and alphabetical metadata, elements or bytes.
    int idx[16];
    int m = n_in < 16 ? n_in : 16;
    for (int i = 0; i < m; i++) idx[i] = i;
    for (int i = 1; i < m; i++) {
        int key = idx[i];
        long long ks = in_sizes[key];
        int j = i - 1;
        while (j >= 0 && (long long)in_sizes[idx[j]] > ks) {
            idx[j + 1] = idx[j]; j--;
        }
        idx[j + 1] = key;
    }
    if (m < 4) return;
    const float* g1c = (const float*)d_in[idx[0]];      // F_g1_coarse
    const float* gkc = (const float*)d_in[idx[1]];      // F_gk_coarse
    const float* g1f = (const float*)d_in[idx[m - 2]];  // F_g1_fine
    const float* gkf = (const float*)d_in[idx[m - 1]];  // F_gk_fine
    float* out = (float*)d_out;

    norms_kernel<<<(B_ * HC_ * WC_ + B_ * HF_ * WF_) / 8, 256>>>(g1c, g1f);

    dim3 gc(HC_ * WC_ / 32, B_);
    coarse_kernel<<<gc, 256>>>(g1c, gkc, out);

    dim3 gf(WC_, HC_, B_);
    fine_kernel<<<gf, 128>>>(g1f, gkf, out + B_ * HC_ * WC_ * 2);
}

// round 8
// speedup vs baseline: 1.1669x; 1.1669x over previous
#include <cuda_runtime.h>
#include <cstdint>

// Problem constants
#define B_  4
#define HC_ 32
#define WC_ 32
#define KC_ 1024
#define HF_ 128
#define WF_ 128
#define KF_ 256
#define DC_ 4

__device__ float g_anorm[B_ * HC_ * WC_];   // coarse candidate norms
__device__ float g_fnorm[B_ * HF_ * WF_];   // fine candidate norms
__device__ int   g_cm[B_ * HC_ * WC_ * 2];  // coarse result (int scratch for fine stage)

union F2U { unsigned long long u; float2 f; };

__device__ __forceinline__ void ffma2(unsigned long long &d,
                                      unsigned long long a,
                                      unsigned long long b) {
    asm("fma.rn.f32x2 %0, %1, %2, %0;" : "+l"(d) : "l"(a), "l"(b));
}
__device__ __forceinline__ unsigned long long dup2(float x) {
    unsigned long long r;
    asm("mov.b64 %0, {%1, %1};" : "=l"(r) : "f"(x));
    return r;
}

// ---------------------------------------------------------------------------
// Kernel 1: candidate squared norms (one warp per row). At DRAM roofline.
// ---------------------------------------------------------------------------
__global__ void norms_kernel(const float* __restrict__ g1c,
                             const float* __restrict__ g1f) {
    int w    = (blockIdx.x * blockDim.x + threadIdx.x) >> 5;
    int lane = threadIdx.x & 31;
    float s = 0.f;
    if (w < B_ * HC_ * WC_) {
        const float* p = g1c + (size_t)w * KC_;
#pragma unroll
        for (int i = 0; i < KC_ / 32; i++) { float v = p[lane + i * 32]; s += v * v; }
#pragma unroll
        for (int o = 16; o; o >>= 1) s += __shfl_xor_sync(0xFFFFFFFFu, s, o);
        if (lane == 0) g_anorm[w] = s;
    } else if (w < B_ * HC_ * WC_ + B_ * HF_ * WF_) {
        int r = w - B_ * HC_ * WC_;
        const float* p = g1f + (size_t)r * KF_;
#pragma unroll
        for (int i = 0; i < KF_ / 32; i++) { float v = p[lane + i * 32]; s += v * v; }
#pragma unroll
        for (int o = 16; o; o >>= 1) s += __shfl_xor_sync(0xFFFFFFFFu, s, o);
        if (lane == 0) g_fnorm[r] = s;
    }
}

// ---------------------------------------------------------------------------
// Kernel 2: coarse match, f32x2 + register-staged double buffering.
// 256 threads; 32 queries/block x 1024 candidates (4 tiles of 256, BK=16).
// Thread (ty,tx): queries ty*4..+3 (dup-packed broadcast), candidate PAIRS
// g*32+tx, g=0..3 (8 candidates). One __syncthreads per chunk.
// Reduction arrays ALIAS the tile buffers (disjoint lifetime; sync between).
// score = |a|^2 - 2 q.a ; output float32.
// ---------------------------------------------------------------------------
__global__ __launch_bounds__(256, 1)
void coarse_kernel(const float* __restrict__ A,
                   const float* __restrict__ Q,
                   float* __restrict__ out) {
    const int b   = blockIdx.y;
    const int q0  = blockIdx.x * 32;
    const int tid = threadIdx.x;
    const int ty  = tid >> 5;
    const int tx  = tid & 31;

    // 40960 bytes: [0,8192) q tiles, [8192,40960) c tiles.
    // After compute: [0,4224) red_v, [4224,8448) red_i.
    __shared__ __align__(16) unsigned char smem_raw[8192 + 32768];
    typedef float QTile[16][64];
    typedef float CTile[16][256];
    QTile* q_s = reinterpret_cast<QTile*>(smem_raw);            // [2]
    CTile* c_s = reinterpret_cast<CTile*>(smem_raw + 8192);     // [2]
    float (*red_v)[33] = reinterpret_cast<float (*)[33]>(smem_raw);          // [32][33]
    int   (*red_i)[33] = reinterpret_cast<int   (*)[33]>(smem_raw + 4224);   // [32][33]

    const float* Ab = A + (size_t)b * (HC_ * WC_) * KC_;
    const float* Qb = Q + (size_t)b * (HC_ * WC_) * KC_;

    const int qrow = tid >> 3;            // 0..31
    const int qkp  = (tid & 7) * 2;       // 0,2,..,14

    float minv[4]; int mini[4];
#pragma unroll
    for (int r = 0; r < 4; r++) { minv[r] = 3.402823466e38f; mini[r] = 0; }

    float4 ra[4];     // staged A row chunk (cand c0+tid, 16 k)
    float2 rq;        // staged Q chunk

    // preload it = 0
    {
        const float* srcA = Ab + (size_t)tid * KC_;
#pragma unroll
        for (int i = 0; i < 4; i++) ra[i] = *(const float4*)(srcA + i * 4);
        rq = *(const float2*)(Qb + (size_t)(q0 + qrow) * KC_ + qkp);
    }

    unsigned long long acc[4][4];

    for (int it = 0; it < 256; it++) {          // it = tile*64 + ks
        const int bw = it & 1;
        const int ks = it & 63;
        // store staged data into buffer bw
        {
#pragma unroll
            for (int i = 0; i < 4; i++) {
                c_s[bw][i * 4 + 0][tid] = ra[i].x;
                c_s[bw][i * 4 + 1][tid] = ra[i].y;
                c_s[bw][i * 4 + 2][tid] = ra[i].z;
                c_s[bw][i * 4 + 3][tid] = ra[i].w;
            }
            *(float2*)&q_s[bw][qkp][qrow * 2]     = make_float2(rq.x, rq.x);
            *(float2*)&q_s[bw][qkp + 1][qrow * 2] = make_float2(rq.y, rq.y);
        }
        // issue global loads for it+1 (latency hidden by compute below)
        if (it + 1 < 256) {
            const int nt = it + 1;
            const int tile = nt >> 6, nks = nt & 63;
            const float* srcA = Ab + (size_t)(tile * 256 + tid) * KC_ + nks * 16;
#pragma unroll
            for (int i = 0; i < 4; i++) ra[i] = *(const float4*)(srcA + i * 4);
            rq = *(const float2*)(Qb + (size_t)(q0 + qrow) * KC_ + nks * 16 + qkp);
        }
        __syncthreads();

        if (ks == 0) {
#pragma unroll
            for (int r = 0; r < 4; r++)
#pragma unroll
                for (int g = 0; g < 4; g++) acc[r][g] = 0ULL;
        }
#pragma unroll
        for (int k = 0; k < 16; k++) {
            unsigned long long qv[4], cv[4];
#pragma unroll
            for (int r = 0; r < 4; r++)
                qv[r] = *(const unsigned long long*)&q_s[bw][k][(ty * 4 + r) * 2];
#pragma unroll
            for (int g = 0; g < 4; g++)
                cv[g] = *(const unsigned long long*)&c_s[bw][k][(g * 32 + tx) * 2];
#pragma unroll
            for (int r = 0; r < 4; r++)
#pragma unroll
                for (int g = 0; g < 4; g++) ffma2(acc[r][g], qv[r], cv[g]);
        }
        if (ks == 63) {
            const int c0 = (it >> 6) * 256;
#pragma unroll
            for (int g = 0; g < 4; g++) {
#pragma unroll
                for (int h = 0; h < 2; h++) {
                    int cand = c0 + (g * 32 + tx) * 2 + h;
                    float an = g_anorm[b * (HC_ * WC_) + cand];
#pragma unroll
                    for (int r = 0; r < 4; r++) {
                        F2U u; u.u = acc[r][g];
                        float dot = h ? u.f.y : u.f.x;
                        float s = an - 2.f * dot;
                        if (s < minv[r] || (s == minv[r] && cand < mini[r])) {
                            minv[r] = s; mini[r] = cand;
                        }
                    }
                }
            }
        }
    }

    // All compute done; buffers may now be reused for the reduction.
    __syncthreads();
#pragma unroll
    for (int r = 0; r < 4; r++) {
        red_v[ty * 4 + r][tx] = minv[r];
        red_i[ty * 4 + r][tx] = mini[r];
    }
    __syncthreads();
    if (tid < 32) {
        float bv = red_v[tid][0]; int bi = red_i[tid][0];
        for (int t = 1; t < 32; t++) {
            float v = red_v[tid][t]; int i2 = red_i[tid][t];
            if (v < bv || (v == bv && i2 < bi)) { bv = v; bi = i2; }
        }
        int q = q0 + tid;
        int ro = bi >> 5, co = bi & 31;
        out[(b * (HC_ * WC_) + q) * 2 + 0] = (float)ro;
        out[(b * (HC_ * WC_) + q) * 2 + 1] = (float)co;
        g_cm[(b * (HC_ * WC_) + q) * 2 + 0] = ro;
        g_cm[(b * (HC_ * WC_) + q) * 2 + 1] = co;
    }
}

// ---------------------------------------------------------------------------
// Kernel 3: fine match, f32x2, SINGLE 160-slot pass. One block (128 thr) per
// coarse cell. 16 queries x 144 candidates (+16 dead slots). Thread
// (qg=warp, cg=lane): queries qg*4..+3, candidate pairs {cg, 32+cg,
// 64+(cg&15)}. Lanes cg>=16 in group 2 duplicate cg-16's candidates (same
// score+index -> harmless in min-reduce); slots >=144 killed by guard.
// Duplicated candidates bitwise-equal -> smallest-index tie-break ==
// jnp.argmin first-min.
// ---------------------------------------------------------------------------
__global__ __launch_bounds__(128)
void fine_kernel(const float* __restrict__ F1,
                 const float* __restrict__ FK,
                 float* __restrict__ out) {
    const int b   = blockIdx.z;
    const int ci  = blockIdx.y;
    const int cj  = blockIdx.x;
    const int tid = threadIdx.x;

    __shared__ float q_t[KF_][16];                 // 16 KB
    __shared__ __align__(16) float c_t[32][160];   // 20 KB  (pairs: cand = 2p+h)
    __shared__ int nbr_r[9], nbr_c[9];
    __shared__ float red_v[16][33];
    __shared__ int   red_i[16][33];

    if (tid < 9) {
        int di = tid / 3 - 1, dj = tid % 3 - 1;
        int ii = min(max(ci + di, 0), HC_ - 1);
        int jj = min(max(cj + dj, 0), WC_ - 1);
        const int* p = g_cm + ((b * HC_ + ii) * WC_ + jj) * 2;
        nbr_r[tid] = min(max(p[0], 0), HC_ - 1);
        nbr_c[tid] = min(max(p[1], 0), WC_ - 1);
    }
    const float* QB = FK + (((size_t)(b * HF_ + ci * DC_) * WF_) + cj * DC_) * KF_;
    for (int idx = tid; idx < 16 * KF_; idx += 128) {
        int p = idx >> 8, k = idx & (KF_ - 1);
        q_t[k][p] = QB[(((p >> 2) * WF_) + (p & 3)) * KF_ + k];
    }

    const int qg = tid >> 5;
    const int cg = tid & 31;
    const int cg16 = cg & 15;

    float minv[4]; int mini[4];
#pragma unroll
    for (int r = 0; r < 4; r++) { minv[r] = 3.402823466e38f; mini[r] = 0; }

    const float* F1b = F1 + (size_t)b * HF_ * WF_ * KF_;
    const float* fnb = g_fnorm + b * HF_ * WF_;

    unsigned long long acc[4][3];
#pragma unroll
    for (int r = 0; r < 4; r++)
#pragma unroll
        for (int g = 0; g < 3; g++) acc[r][g] = 0ULL;

    __syncthreads();   // nbr + q_t ready

    for (int ksub = 0; ksub < KF_ / 32; ksub++) {
        // stage candidate rows 0..143 (k chunk of 32) into c_t[k][row]
        for (int row = tid; row < 144; row += 128) {
            int n = row >> 4, p2 = row & 15;
            int rr = nbr_r[n] * DC_ + (p2 >> 2);
            int c2 = nbr_c[n] * DC_ + (p2 & 3);
            const float* src = F1b + ((size_t)rr * WF_ + c2) * KF_ + ksub * 32;
#pragma unroll
            for (int i = 0; i < 8; i++) {
                float4 v = *(const float4*)(src + i * 4);
                c_t[i * 4 + 0][row] = v.x;
                c_t[i * 4 + 1][row] = v.y;
                c_t[i * 4 + 2][row] = v.z;
                c_t[i * 4 + 3][row] = v.w;
            }
        }
        __syncthreads();
        const int kb = ksub * 32;
#pragma unroll 8
        for (int kl = 0; kl < 32; kl++) {
            unsigned long long qd[4];
#pragma unroll
            for (int r = 0; r < 4; r++) qd[r] = dup2(q_t[kb + kl][qg * 4 + r]);
            unsigned long long cv0 = *(const unsigned long long*)&c_t[kl][cg * 2];
            unsigned long long cv1 = *(const unsigned long long*)&c_t[kl][64 + cg * 2];
            unsigned long long cv2 = *(const unsigned long long*)&c_t[kl][128 + cg16 * 2];
#pragma unroll
            for (int r = 0; r < 4; r++) {
                ffma2(acc[r][0], qd[r], cv0);
                ffma2(acc[r][1], qd[r], cv1);
                ffma2(acc[r][2], qd[r], cv2);
            }
        }
        __syncthreads();
    }

    // epilogue: slots -> candidates
#pragma unroll
    for (int g = 0; g < 3; g++) {
        int base = (g == 0) ? cg * 2 : (g == 1) ? 64 + cg * 2 : 128 + cg16 * 2;
#pragma unroll
        for (int h = 0; h < 2; h++) {
            int cand = base + h;
            if (cand < 144) {
                int n = cand >> 4, p2 = cand & 15;
                int rr = nbr_r[n] * DC_ + (p2 >> 2);
                int c2 = nbr_c[n] * DC_ + (p2 & 3);
                float fn = fnb[rr * WF_ + c2];
#pragma unroll
                for (int r = 0; r < 4; r++) {
                    F2U u; u.u = acc[r][g];
                    float dot = h ? u.f.y : u.f.x;
                    float s = fn - 2.f * dot;
                    if (s < minv[r] || (s == minv[r] && cand < mini[r])) {
                        minv[r] = s; mini[r] = cand;
                    }
                }
            }
        }
    }

#pragma unroll
    for (int r = 0; r < 4; r++) {
        red_v[qg * 4 + r][cg] = minv[r];
        red_i[qg * 4 + r][cg] = mini[r];
    }
    __syncthreads();
    if (tid < 16) {
        float bv = red_v[tid][0]; int bi = red_i[tid][0];
        for (int t = 1; t < 32; t++) {
            float v = red_v[tid][t]; int i2 = red_i[tid][t];
            if (v < bv || (v == bv && i2 < bi)) { bv = v; bi = i2; }
        }
        int n = bi >> 4, p2 = bi & 15;
        int rr = nbr_r[n] * DC_ + (p2 >> 2);
        int c2 = nbr_c[n] * DC_ + (p2 & 3);
        int R = ci * DC_ + (tid >> 2);
        int C = cj * DC_ + (tid & 3);
        float* o = out + (((size_t)(b * HF_ + R) * WF_) + C) * 2;
        o[0] = (float)rr; o[1] = (float)c2;
    }
}

// ---------------------------------------------------------------------------
extern "C" void kernel_launch(void* const* d_in, const int* in_sizes, int n_in,
                              void* d_out, int out_size) {
    // Size-sorted binding (two smallest = coarse g1,gk; two largest = fine).
    int idx[16];
    int m = n_in < 16 ? n_in : 16;
    for (int i = 0; i < m; i++) idx[i] = i;
    for (int i = 1; i < m; i++) {
        int key = idx[i];
        long long ks = in_sizes[key];
        int j = i - 1;
        while (j >= 0 && (long long)in_sizes[idx[j]] > ks) {
            idx[j + 1] = idx[j]; j--;
        }
        idx[j + 1] = key;
    }
    if (m < 4) return;
    const float* g1c = (const float*)d_in[idx[0]];      // F_g1_coarse
    const float* gkc = (const float*)d_in[idx[1]];      // F_gk_coarse
    const float* g1f = (const float*)d_in[idx[m - 2]];  // F_g1_fine
    const float* gkf = (const float*)d_in[idx[m - 1]];  // F_gk_fine
    float* out = (float*)d_out;

    norms_kernel<<<(B_ * HC_ * WC_ + B_ * HF_ * WF_) / 8, 256>>>(g1c, g1f);

    dim3 gc(HC_ * WC_ / 32, B_);
    coarse_kernel<<<gc, 256>>>(g1c, gkc, out);

    dim3 gf(WC_, HC_, B_);
    fine_kernel<<<gf, 128>>>(g1f, gkf, out + B_ * HC_ * WC_ * 2);
}

// round 9
// speedup vs baseline: 1.1832x; 1.0140x over previous
#include <cuda_runtime.h>
#include <cstdint>

// Problem constants
#define B_  4
#define HC_ 32
#define WC_ 32
#define KC_ 1024
#define HF_ 128
#define WF_ 128
#define KF_ 256
#define DC_ 4

__device__ float g_anorm[B_ * HC_ * WC_];   // coarse candidate norms
__device__ float g_fnorm[B_ * HF_ * WF_];   // fine candidate norms
__device__ int   g_cm[B_ * HC_ * WC_ * 2];  // coarse result (int scratch for fine)
__device__ float g_pv[B_ * HC_ * WC_ * 2];  // coarse partial min value  [q][split]
__device__ int   g_pi[B_ * HC_ * WC_ * 2];  // coarse partial min index  [q][split]

union F2U { unsigned long long u; float2 f; };

__device__ __forceinline__ void ffma2(unsigned long long &d,
                                      unsigned long long a,
                                      unsigned long long b) {
    asm("fma.rn.f32x2 %0, %1, %2, %0;" : "+l"(d) : "l"(a), "l"(b));
}
__device__ __forceinline__ unsigned long long dup2(float x) {
    unsigned long long r;
    asm("mov.b64 %0, {%1, %1};" : "=l"(r) : "f"(x));
    return r;
}

// ---------------------------------------------------------------------------
// Kernel 1: candidate squared norms (one warp per row). At DRAM roofline.
// ---------------------------------------------------------------------------
__global__ void norms_kernel(const float* __restrict__ g1c,
                             const float* __restrict__ g1f) {
    int w    = (blockIdx.x * blockDim.x + threadIdx.x) >> 5;
    int lane = threadIdx.x & 31;
    float s = 0.f;
    if (w < B_ * HC_ * WC_) {
        const float* p = g1c + (size_t)w * KC_;
#pragma unroll
        for (int i = 0; i < KC_ / 32; i++) { float v = p[lane + i * 32]; s += v * v; }
#pragma unroll
        for (int o = 16; o; o >>= 1) s += __shfl_xor_sync(0xFFFFFFFFu, s, o);
        if (lane == 0) g_anorm[w] = s;
    } else if (w < B_ * HC_ * WC_ + B_ * HF_ * WF_) {
        int r = w - B_ * HC_ * WC_;
        const float* p = g1f + (size_t)r * KF_;
#pragma unroll
        for (int i = 0; i < KF_ / 32; i++) { float v = p[lane + i * 32]; s += v * v; }
#pragma unroll
        for (int o = 16; o; o >>= 1) s += __shfl_xor_sync(0xFFFFFFFFu, s, o);
        if (lane == 0) g_fnorm[r] = s;
    }
}

// ---------------------------------------------------------------------------
// Kernel 2: coarse match (candidate-split). Grid (32 qblk, 4 batch, 2 split).
// Each block: 32 queries x 512 candidates (2 tiles of 256), BK=8, double
// buffered, 20.6 KB smem -> 2 blocks/SM (16 warps). Writes per-split partial
// (min, argmin) to g_pv/g_pi; merge_kernel combines. f32x2 packed math.
// score = |a|^2 - 2 q.a
// ---------------------------------------------------------------------------
__global__ __launch_bounds__(256, 2)
void coarse_kernel(const float* __restrict__ A,
                   const float* __restrict__ Q) {
    const int b    = blockIdx.y;
    const int q0   = blockIdx.x * 32;
    const int S    = blockIdx.z * 512;       // candidate split base
    const int tid  = threadIdx.x;
    const int ty   = tid >> 5;
    const int tx   = tid & 31;

    // raw smem 20608 B: q_s [2][8][66] at 0 (4224 B), c_s [2][8][256] at 4224.
    // After compute, red_v [32][33] at 0 (4224 B), red_i at 4224 (4224 B).
    __shared__ __align__(16) unsigned char smem_raw[4224 + 16384];
    typedef float QTile[8][66];
    typedef float CTile[8][256];
    QTile* q_s = reinterpret_cast<QTile*>(smem_raw);           // [2]
    CTile* c_s = reinterpret_cast<CTile*>(smem_raw + 4224);    // [2]
    float (*red_v)[33] = reinterpret_cast<float (*)[33]>(smem_raw);
    int   (*red_i)[33] = reinterpret_cast<int   (*)[33]>(smem_raw + 4224);

    const float* Ab = A + (size_t)b * (HC_ * WC_) * KC_;
    const float* Qb = Q + (size_t)b * (HC_ * WC_) * KC_;

    const int qrow = tid >> 3;            // 0..31
    const int qk   = tid & 7;             // 0..7

    float minv[4]; int mini[4];
#pragma unroll
    for (int r = 0; r < 4; r++) { minv[r] = 3.402823466e38f; mini[r] = 0; }

    float4 ra[2];   // staged A row chunk (8 k)
    float  rq;      // staged Q value

    // preload it = 0 (ctile 0, ks 0)
    {
        const float* srcA = Ab + (size_t)(S + tid) * KC_;
        ra[0] = *(const float4*)(srcA);
        ra[1] = *(const float4*)(srcA + 4);
        rq = Qb[(size_t)(q0 + qrow) * KC_ + qk];
    }

    unsigned long long acc[4][4];

    for (int it = 0; it < 256; it++) {        // it = ctile*128 + ks
        const int bw = it & 1;
        const int ks = it & 127;
        // store staged data into buffer bw
        {
#pragma unroll
            for (int i = 0; i < 2; i++) {
                c_s[bw][i * 4 + 0][tid] = ra[i].x;
                c_s[bw][i * 4 + 1][tid] = ra[i].y;
                c_s[bw][i * 4 + 2][tid] = ra[i].z;
                c_s[bw][i * 4 + 3][tid] = ra[i].w;
            }
            *(float2*)&q_s[bw][qk][qrow * 2] = make_float2(rq, rq);
        }
        // prefetch it+1
        if (it + 1 < 256) {
            const int nt = it + 1;
            const int nct = nt >> 7, nks = nt & 127;
            const float* srcA = Ab + (size_t)(S + nct * 256 + tid) * KC_ + nks * 8;
            ra[0] = *(const float4*)(srcA);
            ra[1] = *(const float4*)(srcA + 4);
            rq = Qb[(size_t)(q0 + qrow) * KC_ + nks * 8 + qk];
        }
        __syncthreads();

        if (ks == 0) {
#pragma unroll
            for (int r = 0; r < 4; r++)
#pragma unroll
                for (int g = 0; g < 4; g++) acc[r][g] = 0ULL;
        }
#pragma unroll
        for (int k = 0; k < 8; k++) {
            unsigned long long qv[4], cv[4];
#pragma unroll
            for (int r = 0; r < 4; r++)
                qv[r] = *(const unsigned long long*)&q_s[bw][k][(ty * 4 + r) * 2];
#pragma unroll
            for (int g = 0; g < 4; g++)
                cv[g] = *(const unsigned long long*)&c_s[bw][k][(g * 32 + tx) * 2];
#pragma unroll
            for (int r = 0; r < 4; r++)
#pragma unroll
                for (int g = 0; g < 4; g++) ffma2(acc[r][g], qv[r], cv[g]);
        }
        if (ks == 127) {
            const int c0 = S + (it >> 7) * 256;
#pragma unroll
            for (int g = 0; g < 4; g++) {
#pragma unroll
                for (int h = 0; h < 2; h++) {
                    int cand = c0 + (g * 32 + tx) * 2 + h;
                    float an = g_anorm[b * (HC_ * WC_) + cand];
#pragma unroll
                    for (int r = 0; r < 4; r++) {
                        F2U u; u.u = acc[r][g];
                        float dot = h ? u.f.y : u.f.x;
                        float s = an - 2.f * dot;
                        if (s < minv[r] || (s == minv[r] && cand < mini[r])) {
                            minv[r] = s; mini[r] = cand;
                        }
                    }
                }
            }
        }
    }

    // buffers reusable now
    __syncthreads();
#pragma unroll
    for (int r = 0; r < 4; r++) {
        red_v[ty * 4 + r][tx] = minv[r];
        red_i[ty * 4 + r][tx] = mini[r];
    }
    __syncthreads();
    if (tid < 32) {
        float bv = red_v[tid][0]; int bi = red_i[tid][0];
        for (int t = 1; t < 32; t++) {
            float v = red_v[tid][t]; int i2 = red_i[tid][t];
            if (v < bv || (v == bv && i2 < bi)) { bv = v; bi = i2; }
        }
        int q = b * (HC_ * WC_) + q0 + tid;
        g_pv[q * 2 + blockIdx.z] = bv;
        g_pi[q * 2 + blockIdx.z] = bi;
    }
}

// ---------------------------------------------------------------------------
// Kernel 2b: merge the two candidate-split partials per query.
// Split-0 indices are all < split-1 indices, so (v1<v0 || equal->smaller idx)
// preserves jnp.argmin first-min semantics.
// ---------------------------------------------------------------------------
__global__ void merge_kernel(float* __restrict__ out) {
    int q = blockIdx.x * blockDim.x + threadIdx.x;
    if (q >= B_ * HC_ * WC_) return;
    float v0 = g_pv[q * 2 + 0], v1 = g_pv[q * 2 + 1];
    int   i0 = g_pi[q * 2 + 0], i1 = g_pi[q * 2 + 1];
    int bi = (v1 < v0 || (v1 == v0 && i1 < i0)) ? i1 : i0;
    int ro = bi >> 5, co = bi & 31;
    out[q * 2 + 0] = (float)ro;
    out[q * 2 + 1] = (float)co;
    g_cm[q * 2 + 0] = ro;
    g_cm[q * 2 + 1] = co;
}

// ---------------------------------------------------------------------------
// Kernel 3: fine match, f32x2, single 160-slot pass. One block (128 thr) per
// coarse cell. 16 queries x 144 candidates (+16 dead slots). Duplicated
// candidates produce bitwise-equal scores -> smallest-index tie-break ==
// jnp.argmin first-min.
// ---------------------------------------------------------------------------
__global__ __launch_bounds__(128)
void fine_kernel(const float* __restrict__ F1,
                 const float* __restrict__ FK,
                 float* __restrict__ out) {
    const int b   = blockIdx.z;
    const int ci  = blockIdx.y;
    const int cj  = blockIdx.x;
    const int tid = threadIdx.x;

    __shared__ float q_t[KF_][16];                 // 16 KB
    __shared__ __align__(16) float c_t[32][160];   // 20 KB
    __shared__ int nbr_r[9], nbr_c[9];
    __shared__ float red_v[16][33];
    __shared__ int   red_i[16][33];

    if (tid < 9) {
        int di = tid / 3 - 1, dj = tid % 3 - 1;
        int ii = min(max(ci + di, 0), HC_ - 1);
        int jj = min(max(cj + dj, 0), WC_ - 1);
        const int* p = g_cm + ((b * HC_ + ii) * WC_ + jj) * 2;
        nbr_r[tid] = min(max(p[0], 0), HC_ - 1);
        nbr_c[tid] = min(max(p[1], 0), WC_ - 1);
    }
    const float* QB = FK + (((size_t)(b * HF_ + ci * DC_) * WF_) + cj * DC_) * KF_;
    for (int idx = tid; idx < 16 * KF_; idx += 128) {
        int p = idx >> 8, k = idx & (KF_ - 1);
        q_t[k][p] = QB[(((p >> 2) * WF_) + (p & 3)) * KF_ + k];
    }

    const int qg = tid >> 5;
    const int cg = tid & 31;
    const int cg16 = cg & 15;

    float minv[4]; int mini[4];
#pragma unroll
    for (int r = 0; r < 4; r++) { minv[r] = 3.402823466e38f; mini[r] = 0; }

    const float* F1b = F1 + (size_t)b * HF_ * WF_ * KF_;
    const float* fnb = g_fnorm + b * HF_ * WF_;

    unsigned long long acc[4][3];
#pragma unroll
    for (int r = 0; r < 4; r++)
#pragma unroll
        for (int g = 0; g < 3; g++) acc[r][g] = 0ULL;

    __syncthreads();

    for (int ksub = 0; ksub < KF_ / 32; ksub++) {
        for (int row = tid; row < 144; row += 128) {
            int n = row >> 4, p2 = row & 15;
            int rr = nbr_r[n] * DC_ + (p2 >> 2);
            int c2 = nbr_c[n] * DC_ + (p2 & 3);
            const float* src = F1b + ((size_t)rr * WF_ + c2) * KF_ + ksub * 32;
#pragma unroll
            for (int i = 0; i < 8; i++) {
                float4 v = *(const float4*)(src + i * 4);
                c_t[i * 4 + 0][row] = v.x;
                c_t[i * 4 + 1][row] = v.y;
                c_t[i * 4 + 2][row] = v.z;
                c_t[i * 4 + 3][row] = v.w;
            }
        }
        __syncthreads();
        const int kb = ksub * 32;
#pragma unroll 8
        for (int kl = 0; kl < 32; kl++) {
            unsigned long long qd[4];
#pragma unroll
            for (int r = 0; r < 4; r++) qd[r] = dup2(q_t[kb + kl][qg * 4 + r]);
            unsigned long long cv0 = *(const unsigned long long*)&c_t[kl][cg * 2];
            unsigned long long cv1 = *(const unsigned long long*)&c_t[kl][64 + cg * 2];
            unsigned long long cv2 = *(const unsigned long long*)&c_t[kl][128 + cg16 * 2];
#pragma unroll
            for (int r = 0; r < 4; r++) {
                ffma2(acc[r][0], qd[r], cv0);
                ffma2(acc[r][1], qd[r], cv1);
                ffma2(acc[r][2], qd[r], cv2);
            }
        }
        __syncthreads();
    }

#pragma unroll
    for (int g = 0; g < 3; g++) {
        int base = (g == 0) ? cg * 2 : (g == 1) ? 64 + cg * 2 : 128 + cg16 * 2;
#pragma unroll
        for (int h = 0; h < 2; h++) {
            int cand = base + h;
            if (cand < 144) {
                int n = cand >> 4, p2 = cand & 15;
                int rr = nbr_r[n] * DC_ + (p2 >> 2);
                int c2 = nbr_c[n] * DC_ + (p2 & 3);
                float fn = fnb[rr * WF_ + c2];
#pragma unroll
                for (int r = 0; r < 4; r++) {
                    F2U u; u.u = acc[r][g];
                    float dot = h ? u.f.y : u.f.x;
                    float s = fn - 2.f * dot;
                    if (s < minv[r] || (s == minv[r] && cand < mini[r])) {
                        minv[r] = s; mini[r] = cand;
                    }
                }
            }
        }
    }

#pragma unroll
    for (int r = 0; r < 4; r++) {
        red_v[qg * 4 + r][cg] = minv[r];
        red_i[qg * 4 + r][cg] = mini[r];
    }
    __syncthreads();
    if (tid < 16) {
        float bv = red_v[tid][0]; int bi = red_i[tid][0];
        for (int t = 1; t < 32; t++) {
            float v = red_v[tid][t]; int i2 = red_i[tid][t];
            if (v < bv || (v == bv && i2 < bi)) { bv = v; bi = i2; }
        }
        int n = bi >> 4, p2 = bi & 15;
        int rr = nbr_r[n] * DC_ + (p2 >> 2);
        int c2 = nbr_c[n] * DC_ + (p2 & 3);
        int R = ci * DC_ + (tid >> 2);
        int C = cj * DC_ + (tid & 3);
        float* o = out + (((size_t)(b * HF_ + R) * WF_) + C) * 2;
        o[0] = (float)rr; o[1] = (float)c2;
    }
}

// ---------------------------------------------------------------------------
extern "C" void kernel_launch(void* const* d_in, const int* in_sizes, int n_in,
                              void* d_out, int out_size) {
    // Size-sorted binding (two smallest = coarse g1,gk; two largest = fine).
    int idx[16];
    int m = n_in < 16 ? n_in : 16;
    for (int i = 0; i < m; i++) idx[i] = i;
    for (int i = 1; i < m; i++) {
        int key = idx[i];
        long long ks = in_sizes[key];
        int j = i - 1;
        while (j >= 0 && (long long)in_sizes[idx[j]] > ks) {
            idx[j + 1] = idx[j]; j--;
        }
        idx[j + 1] = key;
    }
    if (m < 4) return;
    const float* g1c = (const float*)d_in[idx[0]];      // F_g1_coarse
    const float* gkc = (const float*)d_in[idx[1]];      // F_gk_coarse
    const float* g1f = (const float*)d_in[idx[m - 2]];  // F_g1_fine
    const float* gkf = (const float*)d_in[idx[m - 1]];  // F_gk_fine
    float* out = (float*)d_out;

    norms_kernel<<<(B_ * HC_ * WC_ + B_ * HF_ * WF_) / 8, 256>>>(g1c, g1f);

    dim3 gc(HC_ * WC_ / 32, B_, 2);
    coarse_kernel<<<gc, 256>>>(g1c, gkc);

    merge_kernel<<<(B_ * HC_ * WC_ + 255) / 256, 256>>>(out);

    dim3 gf(WC_, HC_, B_);
    fine_kernel<<<gf, 128>>>(g1f, gkf, out + B_ * HC_ * WC_ * 2);
}

// round 10
// speedup vs baseline: 1.4262x; 1.2053x over previous
#include <cuda_runtime.h>
#include <cstdint>

#define B_  4
#define HC_ 32
#define WC_ 32
#define KC_ 1024
#define HF_ 128
#define WF_ 128
#define KF_ 256
#define DC_ 4

__device__ float g_anorm[B_ * HC_ * WC_];
__device__ float g_fnorm[B_ * HF_ * WF_];
__device__ int   g_cm[B_ * HC_ * WC_ * 2];
__device__ float g_pv[B_ * HC_ * WC_ * 2];  // [q][split]
__device__ int   g_pi[B_ * HC_ * WC_ * 2];

union F2U { unsigned long long u; float2 f; };

__device__ __forceinline__ void ffma2(unsigned long long &d,
                                      unsigned long long a,
                                      unsigned long long b) {
    asm("fma.rn.f32x2 %0, %1, %2, %0;" : "+l"(d) : "l"(a), "l"(b));
}
__device__ __forceinline__ unsigned long long dup2(float x) {
    unsigned long long r;
    asm("mov.b64 %0, {%1, %1};" : "=l"(r) : "f"(x));
    return r;
}

// ---------------------------------------------------------------------------
// Kernel 1: candidate squared norms (one warp per row). DRAM-roofline bound.
// ---------------------------------------------------------------------------
__global__ void norms_kernel(const float* __restrict__ g1c,
                             const float* __restrict__ g1f) {
    int w    = (blockIdx.x * blockDim.x + threadIdx.x) >> 5;
    int lane = threadIdx.x & 31;
    float s = 0.f;
    if (w < B_ * HC_ * WC_) {
        const float* p = g1c + (size_t)w * KC_;
#pragma unroll
        for (int i = 0; i < KC_ / 32; i++) { float v = p[lane + i * 32]; s += v * v; }
#pragma unroll
        for (int o = 16; o; o >>= 1) s += __shfl_xor_sync(0xFFFFFFFFu, s, o);
        if (lane == 0) g_anorm[w] = s;
    } else if (w < B_ * HC_ * WC_ + B_ * HF_ * WF_) {
        int r = w - B_ * HC_ * WC_;
        const float* p = g1f + (size_t)r * KF_;
#pragma unroll
        for (int i = 0; i < KF_ / 32; i++) { float v = p[lane + i * 32]; s += v * v; }
#pragma unroll
        for (int o = 16; o; o >>= 1) s += __shfl_xor_sync(0xFFFFFFFFu, s, o);
        if (lane == 0) g_fnorm[r] = s;
    }
}

// ---------------------------------------------------------------------------
// Kernel 2: coarse match. Block 256 thr = 8 warps; 32 queries x 512 cands
// (split blockIdx.z of 2). Warp w: query-half qh=w>>2, cand-quarter cq=w&3.
// Lane (qq=cg>>3, ss=cg&7): 4 queries x 16 cands (8 f32x2 pairs).
// All candidate LDS are contiguous 128B/warp (1 wf); q is one LDS.128
// broadcast; dup2 into registers. k-only loop, BK=8 double-buffered.
// score = |a|^2 - 2 q.a ; per-split partial argmin -> g_pv/g_pi.
// ---------------------------------------------------------------------------
__global__ __launch_bounds__(256, 2)
void coarse_kernel(const float* __restrict__ A,
                   const float* __restrict__ Q) {
    const int b   = blockIdx.y;
    const int q0  = blockIdx.x * 32;
    const int S   = blockIdx.z * 512;
    const int tid = threadIdx.x;
    const int w   = tid >> 5;
    const int cg  = tid & 31;
    const int qh  = w >> 2;     // 0..1
    const int cq  = w & 3;      // 0..3
    const int qq  = cg >> 3;    // 0..3
    const int ss  = cg & 7;     // 0..7

    __shared__ float q_s[2][8][32];                      // 2 KB
    __shared__ __align__(16) float c_s[2][8][512];       // 32 KB
    __shared__ float red_v[32][5];
    __shared__ int   red_i[32][5];

    const float* Ab = A + (size_t)b * (HC_ * WC_) * KC_;
    const float* Qb = Q + (size_t)b * (HC_ * WC_) * KC_;

    // staging roles: thread stages cand rows (S+tid) and (S+256+tid), plus
    // one q element (p=tid>>3, k=tid&7).
    float4 ra0, ra1, ra2, ra3; float rq;
    {
        const float* s0 = Ab + (size_t)(S + tid) * KC_;
        ra0 = *(const float4*)(s0);     ra1 = *(const float4*)(s0 + 4);
        const float* s1 = Ab + (size_t)(S + 256 + tid) * KC_;
        ra2 = *(const float4*)(s1);     ra3 = *(const float4*)(s1 + 4);
        rq = Qb[(size_t)(q0 + (tid >> 3)) * KC_ + (tid & 7)];
    }

    unsigned long long acc[4][8];
#pragma unroll
    for (int r = 0; r < 4; r++)
#pragma unroll
        for (int g = 0; g < 8; g++) acc[r][g] = 0ULL;

    for (int ck = 0; ck < 128; ck++) {
        const int bw = ck & 1;
        {
            c_s[bw][0][tid] = ra0.x; c_s[bw][1][tid] = ra0.y;
            c_s[bw][2][tid] = ra0.z; c_s[bw][3][tid] = ra0.w;
            c_s[bw][4][tid] = ra1.x; c_s[bw][5][tid] = ra1.y;
            c_s[bw][6][tid] = ra1.z; c_s[bw][7][tid] = ra1.w;
            c_s[bw][0][tid + 256] = ra2.x; c_s[bw][1][tid + 256] = ra2.y;
            c_s[bw][2][tid + 256] = ra2.z; c_s[bw][3][tid + 256] = ra2.w;
            c_s[bw][4][tid + 256] = ra3.x; c_s[bw][5][tid + 256] = ra3.y;
            c_s[bw][6][tid + 256] = ra3.z; c_s[bw][7][tid + 256] = ra3.w;
            q_s[bw][tid & 7][tid >> 3] = rq;
        }
        if (ck + 1 < 128) {
            const int k0 = (ck + 1) * 8;
            const float* s0 = Ab + (size_t)(S + tid) * KC_ + k0;
            ra0 = *(const float4*)(s0);     ra1 = *(const float4*)(s0 + 4);
            const float* s1 = Ab + (size_t)(S + 256 + tid) * KC_ + k0;
            ra2 = *(const float4*)(s1);     ra3 = *(const float4*)(s1 + 4);
            rq = Qb[(size_t)(q0 + (tid >> 3)) * KC_ + k0 + (tid & 7)];
        }
        __syncthreads();

#pragma unroll
        for (int k = 0; k < 8; k++) {
            float4 qv = *(const float4*)&q_s[bw][k][qh * 16 + qq * 4];
            unsigned long long qd[4] = { dup2(qv.x), dup2(qv.y),
                                         dup2(qv.z), dup2(qv.w) };
#pragma unroll
            for (int g = 0; g < 4; g++) {
                ulonglong2 cp = *(const ulonglong2*)
                    &c_s[bw][k][cq * 128 + g * 32 + ss * 4];
#pragma unroll
                for (int r = 0; r < 4; r++) {
                    ffma2(acc[r][g * 2],     qd[r], cp.x);
                    ffma2(acc[r][g * 2 + 1], qd[r], cp.y);
                }
            }
        }
        __syncthreads();
    }

    // epilogue: local argmin per query over this thread's 16 cands
#pragma unroll
    for (int r = 0; r < 4; r++) {
        float bv = 3.402823466e38f; int bi = 0;
#pragma unroll
        for (int g = 0; g < 4; g++) {
#pragma unroll
            for (int p2 = 0; p2 < 2; p2++) {
                F2U u; u.u = acc[r][g * 2 + p2];
#pragma unroll
                for (int h = 0; h < 2; h++) {
                    int cand = S + cq * 128 + g * 32 + ss * 4 + p2 * 2 + h;
                    float an = g_anorm[b * (HC_ * WC_) + cand];
                    float dot = h ? u.f.y : u.f.x;
                    float s = an - 2.f * dot;
                    if (s < bv || (s == bv && cand < bi)) { bv = s; bi = cand; }
                }
            }
        }
        // reduce over ss lanes (same qq group)
#pragma unroll
        for (int off = 1; off < 8; off <<= 1) {
            float ov = __shfl_xor_sync(0xFFFFFFFFu, bv, off);
            int   oi = __shfl_xor_sync(0xFFFFFFFFu, bi, off);
            if (ov < bv || (ov == bv && oi < bi)) { bv = ov; bi = oi; }
        }
        if (ss == 0) {
            int ql = qh * 16 + qq * 4 + r;    // 0..31
            red_v[ql][cq] = bv;
            red_i[ql][cq] = bi;
        }
    }
    __syncthreads();
    if (tid < 32) {
        float bv = red_v[tid][0]; int bi = red_i[tid][0];
#pragma unroll
        for (int t = 1; t < 4; t++) {
            float v = red_v[tid][t]; int i2 = red_i[tid][t];
            if (v < bv || (v == bv && i2 < bi)) { bv = v; bi = i2; }
        }
        int q = b * (HC_ * WC_) + q0 + tid;
        g_pv[q * 2 + blockIdx.z] = bv;
        g_pi[q * 2 + blockIdx.z] = bi;
    }
}

// ---------------------------------------------------------------------------
// Kernel 2b: merge the two split partials per query (split-0 indices all
// smaller -> jnp first-min preserved).
// ---------------------------------------------------------------------------
__global__ void merge_kernel(float* __restrict__ out) {
    int q = blockIdx.x * blockDim.x + threadIdx.x;
    if (q >= B_ * HC_ * WC_) return;
    float v0 = g_pv[q * 2 + 0], v1 = g_pv[q * 2 + 1];
    int   i0 = g_pi[q * 2 + 0], i1 = g_pi[q * 2 + 1];
    int bi = (v1 < v0 || (v1 == v0 && i1 < i0)) ? i1 : i0;
    int ro = bi >> 5, co = bi & 31;
    out[q * 2 + 0] = (float)ro;
    out[q * 2 + 1] = (float)co;
    g_cm[q * 2 + 0] = ro;
    g_cm[q * 2 + 1] = co;
}

// ---------------------------------------------------------------------------
// Kernel 3: fine match. Block 288 thr = 9 warps, one per neighbor (16 slots
// each -> zero dead slots). Lane (qq=cg>>3, ss=cg&7): 4 queries x 1 cand
// pair (slots w*16+ss*2,+1). q: one LDS.128 broadcast + dup2; c: one LDS.64
// (64B contiguous, broadcast across qq). Per-slot fp chains in k order ->
// duplicated candidates bitwise-equal -> smallest-index tie-break ==
// jnp.argmin first-min.
// ---------------------------------------------------------------------------
__global__ __launch_bounds__(288, 4)
void fine_kernel(const float* __restrict__ F1,
                 const float* __restrict__ FK,
                 float* __restrict__ out) {
    const int b   = blockIdx.z;
    const int ci  = blockIdx.y;
    const int cj  = blockIdx.x;
    const int tid = threadIdx.x;
    const int w   = tid >> 5;    // 0..8 = neighbor
    const int cg  = tid & 31;
    const int qq  = cg >> 3;     // 0..3
    const int ss  = cg & 7;      // 0..7

    __shared__ float q_t[KF_][16];                  // 16 KB
    __shared__ __align__(16) float c_t[32][144];    // 18 KB
    __shared__ int nbr_r[9], nbr_c[9];
    __shared__ float red_v[16][10];
    __shared__ int   red_i[16][10];

    if (tid < 9) {
        int di = tid / 3 - 1, dj = tid % 3 - 1;
        int ii = min(max(ci + di, 0), HC_ - 1);
        int jj = min(max(cj + dj, 0), WC_ - 1);
        const int* p = g_cm + ((b * HC_ + ii) * WC_ + jj) * 2;
        nbr_r[tid] = min(max(p[0], 0), HC_ - 1);
        nbr_c[tid] = min(max(p[1], 0), WC_ - 1);
    }
    const float* QB = FK + (((size_t)(b * HF_ + ci * DC_) * WF_) + cj * DC_) * KF_;
    for (int idx = tid; idx < 16 * KF_; idx += 288) {
        int p = idx >> 8, k = idx & (KF_ - 1);
        q_t[k][p] = QB[(((p >> 2) * WF_) + (p & 3)) * KF_ + k];
    }

    const float* F1b = F1 + (size_t)b * HF_ * WF_ * KF_;
    const float* fnb = g_fnorm + b * HF_ * WF_;

    unsigned long long acc[4];
#pragma unroll
    for (int r = 0; r < 4; r++) acc[r] = 0ULL;

    __syncthreads();   // nbr + q_t ready

    // staging role: 288 threads = 2 per row (144 rows), half = 16 k each
    const int srow  = tid >> 1;
    const int shalf = tid & 1;
    const int sn = srow >> 4, sp = srow & 15;
    const int s_rr = nbr_r[sn] * DC_ + (sp >> 2);
    const int s_cc = nbr_c[sn] * DC_ + (sp & 3);
    const float* srcbase = F1b + ((size_t)s_rr * WF_ + s_cc) * KF_ + shalf * 16;

    for (int ksub = 0; ksub < 8; ksub++) {
        {
            const float* src = srcbase + ksub * 32;
#pragma unroll
            for (int i = 0; i < 4; i++) {
                float4 v = *(const float4*)(src + i * 4);
                int kk = shalf * 16 + i * 4;
                c_t[kk + 0][srow] = v.x;
                c_t[kk + 1][srow] = v.y;
                c_t[kk + 2][srow] = v.z;
                c_t[kk + 3][srow] = v.w;
            }
        }
        __syncthreads();
        const int kb = ksub * 32;
#pragma unroll 8
        for (int kl = 0; kl < 32; kl++) {
            float4 qv = *(const float4*)&q_t[kb + kl][qq * 4];
            unsigned long long cp = *(const unsigned long long*)
                &c_t[kl][w * 16 + ss * 2];
            ffma2(acc[0], dup2(qv.x), cp);
            ffma2(acc[1], dup2(qv.y), cp);
            ffma2(acc[2], dup2(qv.z), cp);
            ffma2(acc[3], dup2(qv.w), cp);
        }
        __syncthreads();
    }

    // epilogue: this thread's 2 slots, 4 queries
    {
        int slot0 = w * 16 + ss * 2;
        int n0 = w;
        int p0 = slot0 & 15, p1 = (slot0 + 1) & 15;
        int rr0 = nbr_r[n0] * DC_ + (p0 >> 2), cc0 = nbr_c[n0] * DC_ + (p0 & 3);
        int rr1 = nbr_r[n0] * DC_ + (p1 >> 2), cc1 = nbr_c[n0] * DC_ + (p1 & 3);
        float fn0 = fnb[rr0 * WF_ + cc0];
        float fn1 = fnb[rr1 * WF_ + cc1];
#pragma unroll
        for (int r = 0; r < 4; r++) {
            F2U u; u.u = acc[r];
            float s0 = fn0 - 2.f * u.f.x;
            float s1 = fn1 - 2.f * u.f.y;
            float bv; int bi;
            if (s0 <= s1) { bv = s0; bi = slot0; }
            else          { bv = s1; bi = slot0 + 1; }
#pragma unroll
            for (int off = 1; off < 8; off <<= 1) {
                float ov = __shfl_xor_sync(0xFFFFFFFFu, bv, off);
                int   oi = __shfl_xor_sync(0xFFFFFFFFu, bi, off);
                if (ov < bv || (ov == bv && oi < bi)) { bv = ov; bi = oi; }
            }
            if (ss == 0) {
                red_v[qq * 4 + r][w] = bv;
                red_i[qq * 4 + r][w] = bi;
            }
        }
    }
    __syncthreads();
    if (tid < 16) {
        float bv = red_v[tid][0]; int bi = red_i[tid][0];
#pragma unroll
        for (int t = 1; t < 9; t++) {
            float v = red_v[tid][t]; int i2 = red_i[tid][t];
            if (v < bv || (v == bv && i2 < bi)) { bv = v; bi = i2; }
        }
        int n = bi >> 4, p2 = bi & 15;
        int rr = nbr_r[n] * DC_ + (p2 >> 2);
        int c2 = nbr_c[n] * DC_ + (p2 & 3);
        int R = ci * DC_ + (tid >> 2);
        int C = cj * DC_ + (tid & 3);
        float* o = out + (((size_t)(b * HF_ + R) * WF_) + C) * 2;
        o[0] = (float)rr; o[1] = (float)c2;
    }
}

// ---------------------------------------------------------------------------
extern "C" void kernel_launch(void* const* d_in, const int* in_sizes, int n_in,
                              void* d_out, int out_size) {
    int idx[16];
    int m = n_in < 16 ? n_in : 16;
    for (int i = 0; i < m; i++) idx[i] = i;
    for (int i = 1; i < m; i++) {
        int key = idx[i];
        long long ks = in_sizes[key];
        int j = i - 1;
        while (j >= 0 && (long long)in_sizes[idx[j]] > ks) {
            idx[j + 1] = idx[j]; j--;
        }
        idx[j + 1] = key;
    }
    if (m < 4) return;
    const float* g1c = (const float*)d_in[idx[0]];      // F_g1_coarse
    const float* gkc = (const float*)d_in[idx[1]];      // F_gk_coarse
    const float* g1f = (const float*)d_in[idx[m - 2]];  // F_g1_fine
    const float* gkf = (const float*)d_in[idx[m - 1]];  // F_gk_fine
    float* out = (float*)d_out;

    norms_kernel<<<(B_ * HC_ * WC_ + B_ * HF_ * WF_) / 8, 256>>>(g1c, g1f);

    dim3 gc(HC_ * WC_ / 32, B_, 2);
    coarse_kernel<<<gc, 256>>>(g1c, gkc);

    merge_kernel<<<(B_ * HC_ * WC_ + 255) / 256, 256>>>(out);

    dim3 gf(WC_, HC_, B_);
    fine_kernel<<<gf, 288>>>(g1f, gkf, out + B_ * HC_ * WC_ * 2);
}

// round 11
// speedup vs baseline: 1.4670x; 1.0286x over previous
#include <cuda_runtime.h>
#include <cstdint>

#define B_  4
#define HC_ 32
#define WC_ 32
#define KC_ 1024
#define HF_ 128
#define WF_ 128
#define KF_ 256
#define DC_ 4

__device__ float g_anorm[B_ * HC_ * WC_];
__device__ float g_fnorm[B_ * HF_ * WF_];
__device__ int   g_cm[B_ * HC_ * WC_ * 2];
__device__ float g_pv[B_ * HC_ * WC_ * 8];   // [q][split]
__device__ int   g_pi[B_ * HC_ * WC_ * 8];

// ---------------------------------------------------------------------------
// Kernel 1: candidate squared norms (one warp per row). DRAM-roofline bound.
// ---------------------------------------------------------------------------
__global__ void norms_kernel(const float* __restrict__ g1c,
                             const float* __restrict__ g1f) {
    int w    = (blockIdx.x * blockDim.x + threadIdx.x) >> 5;
    int lane = threadIdx.x & 31;
    float s = 0.f;
    if (w < B_ * HC_ * WC_) {
        const float* p = g1c + (size_t)w * KC_;
#pragma unroll
        for (int i = 0; i < KC_ / 32; i++) { float v = p[lane + i * 32]; s += v * v; }
#pragma unroll
        for (int o = 16; o; o >>= 1) s += __shfl_xor_sync(0xFFFFFFFFu, s, o);
        if (lane == 0) g_anorm[w] = s;
    } else if (w < B_ * HC_ * WC_ + B_ * HF_ * WF_) {
        int r = w - B_ * HC_ * WC_;
        const float* p = g1f + (size_t)r * KF_;
#pragma unroll
        for (int i = 0; i < KF_ / 32; i++) { float v = p[lane + i * 32]; s += v * v; }
#pragma unroll
        for (int o = 16; o; o >>= 1) s += __shfl_xor_sync(0xFFFFFFFFu, s, o);
        if (lane == 0) g_fnorm[r] = s;
    }
}

// ---------------------------------------------------------------------------
// Kernel 2: coarse match. Grid (32 qblk, 4 batch, 8 csplit) = 1024 blocks,
// 128 thr, occ 7 -> 1036 slots = one ~full wave. Block: 32 q x 128 cands.
// Warp w: qh=w>>1 (16q), cq=w&1 (64c). Lane: qq=lane>>3 (4q), ss=lane&7.
// Thread tile 4q x 8c, scalar FMA, BK=8 double-buffered, reg prefetch.
// score = |a|^2 - 2 q.a ; partial argmin -> g_pv/g_pi[ q ][ split ].
// ---------------------------------------------------------------------------
__global__ __launch_bounds__(128, 7)
void coarse_kernel(const float* __restrict__ A,
                   const float* __restrict__ Q) {
    const int b    = blockIdx.y;
    const int q0   = blockIdx.x * 32;
    const int cs   = blockIdx.z;
    const int S    = cs * 128;
    const int tid  = threadIdx.x;
    const int w    = tid >> 5;
    const int lane = tid & 31;
    const int qh   = w >> 1;
    const int cq   = w & 1;
    const int qq   = lane >> 3;
    const int ss   = lane & 7;

    __shared__ float q_s[2][8][32];                    // 2 KB
    __shared__ __align__(16) float c_s[2][8][128];     // 8 KB
    __shared__ float red_v[32][3];
    __shared__ int   red_i[32][3];

    const float* Ab = A + (size_t)b * (HC_ * WC_) * KC_;
    const float* Qb = Q + (size_t)b * (HC_ * WC_) * KC_;

    // staging roles: every thread stages c row S+tid (8 k) + one q float2.
    const int qp = tid >> 2;           // 0..31
    const int qk = (tid * 2) & 7;      // 0,2,4,6
    const float* csrc = Ab + (size_t)(S + tid) * KC_;
    const float* qsrc = Qb + (size_t)(q0 + qp) * KC_ + qk;

    float4 ra0, ra1; float2 rq;
    ra0 = *(const float4*)(csrc);
    ra1 = *(const float4*)(csrc + 4);
    rq  = *(const float2*)(qsrc);

    float acc[4][8];
#pragma unroll
    for (int r = 0; r < 4; r++)
#pragma unroll
        for (int j = 0; j < 8; j++) acc[r][j] = 0.f;

    for (int ck = 0; ck < 128; ck++) {
        const int bw = ck & 1;
        c_s[bw][0][tid] = ra0.x; c_s[bw][1][tid] = ra0.y;
        c_s[bw][2][tid] = ra0.z; c_s[bw][3][tid] = ra0.w;
        c_s[bw][4][tid] = ra1.x; c_s[bw][5][tid] = ra1.y;
        c_s[bw][6][tid] = ra1.z; c_s[bw][7][tid] = ra1.w;
        q_s[bw][qk][qp]     = rq.x;
        q_s[bw][qk + 1][qp] = rq.y;
        if (ck + 1 < 128) {
            const int k0 = (ck + 1) * 8;
            ra0 = *(const float4*)(csrc + k0);
            ra1 = *(const float4*)(csrc + k0 + 4);
            rq  = *(const float2*)(qsrc + k0);
        }
        __syncthreads();
#pragma unroll
        for (int k = 0; k < 8; k++) {
            float4 qv = *(const float4*)&q_s[bw][k][qh * 16 + qq * 4];
            float4 c0 = *(const float4*)&c_s[bw][k][cq * 64 + ss * 4];
            float4 c1 = *(const float4*)&c_s[bw][k][cq * 64 + 32 + ss * 4];
            float qr[4] = { qv.x, qv.y, qv.z, qv.w };
            float cc[8] = { c0.x, c0.y, c0.z, c0.w, c1.x, c1.y, c1.z, c1.w };
#pragma unroll
            for (int r = 0; r < 4; r++)
#pragma unroll
                for (int j = 0; j < 8; j++)
                    acc[r][j] = fmaf(qr[r], cc[j], acc[r][j]);
        }
    }

    // epilogue: per-thread argmin over its 8 cands, shfl-reduce over ss.
#pragma unroll
    for (int r = 0; r < 4; r++) {
        float bv = 3.402823466e38f; int bi = 0;
#pragma unroll
        for (int j = 0; j < 8; j++) {
            int cand = S + cq * 64 + ((j < 4) ? (ss * 4 + j) : (32 + ss * 4 + j - 4));
            float an = g_anorm[b * (HC_ * WC_) + cand];
            float s = an - 2.f * acc[r][j];
            if (s < bv || (s == bv && cand < bi)) { bv = s; bi = cand; }
        }
#pragma unroll
        for (int off = 1; off < 8; off <<= 1) {
            float ov = __shfl_xor_sync(0xFFFFFFFFu, bv, off);
            int   oi = __shfl_xor_sync(0xFFFFFFFFu, bi, off);
            if (ov < bv || (ov == bv && oi < bi)) { bv = ov; bi = oi; }
        }
        if (ss == 0) {
            int ql = qh * 16 + qq * 4 + r;
            red_v[ql][cq] = bv;
            red_i[ql][cq] = bi;
        }
    }
    __syncthreads();
    if (tid < 32) {
        float bv = red_v[tid][0]; int bi = red_i[tid][0];
        float v1 = red_v[tid][1]; int i1 = red_i[tid][1];
        if (v1 < bv || (v1 == bv && i1 < bi)) { bv = v1; bi = i1; }
        int q = b * (HC_ * WC_) + q0 + tid;
        g_pv[q * 8 + cs] = bv;
        g_pi[q * 8 + cs] = bi;
    }
}

// ---------------------------------------------------------------------------
// Kernel 2b: merge 8 ordered split partials per query (explicit tie compare
// -> jnp.argmin first-min preserved).
// ---------------------------------------------------------------------------
__global__ void merge_kernel(float* __restrict__ out) {
    int q = blockIdx.x * blockDim.x + threadIdx.x;
    if (q >= B_ * HC_ * WC_) return;
    float bv = g_pv[q * 8]; int bi = g_pi[q * 8];
#pragma unroll
    for (int s = 1; s < 8; s++) {
        float v = g_pv[q * 8 + s]; int i2 = g_pi[q * 8 + s];
        if (v < bv || (v == bv && i2 < bi)) { bv = v; bi = i2; }
    }
    int ro = bi >> 5, co = bi & 31;
    out[q * 2 + 0] = (float)ro;
    out[q * 2 + 1] = (float)co;
    g_cm[q * 2 + 0] = ro;
    g_cm[q * 2 + 1] = co;
}

// ---------------------------------------------------------------------------
// Kernel 3: fine match. Block 160 thr; compute threads tid<144:
// qg=tid/36 (4 queries qg*4..+3), cgi=tid%36 (4 slots cgi*4..+3).
// Per k: 1 LDS.128 q (36-thread broadcast) + 1 LDS.128 c + 16 FMA.
// c chunk [16 k][144 slots] + q chunk [16][16], double-buffered, reg
// prefetch, one sync/chunk. Identical fp chain order for every slot ->
// duplicated candidates bitwise equal -> smallest-slot tie-break ==
// jnp.argmin first-min.
// ---------------------------------------------------------------------------
__global__ __launch_bounds__(160, 6)
void fine_kernel(const float* __restrict__ F1,
                 const float* __restrict__ FK,
                 float* __restrict__ out) {
    const int b   = blockIdx.z;
    const int ci  = blockIdx.y;
    const int cj  = blockIdx.x;
    const int tid = threadIdx.x;

    __shared__ float q_c[2][16][16];                    // 2 KB
    __shared__ __align__(16) float c_c[2][16][148];     // 18.9 KB (pad 148)
    __shared__ int nbr_r[9], nbr_c[9];
    __shared__ float red_v[16][37];
    __shared__ int   red_i[16][37];

    if (tid < 9) {
        int di = tid / 3 - 1, dj = tid % 3 - 1;
        int ii = min(max(ci + di, 0), HC_ - 1);
        int jj = min(max(cj + dj, 0), WC_ - 1);
        const int* p = g_cm + ((b * HC_ + ii) * WC_ + jj) * 2;
        nbr_r[tid] = min(max(p[0], 0), HC_ - 1);
        nbr_c[tid] = min(max(p[1], 0), WC_ - 1);
    }
    __syncthreads();

    const float* F1b = F1 + (size_t)b * HF_ * WF_ * KF_;
    const float* fnb = g_fnorm + b * HF_ * WF_;
    const float* QB  = FK + (((size_t)(b * HF_ + ci * DC_) * WF_) + cj * DC_) * KF_;

    // staging roles
    const bool cstage = (tid < 144);
    const int  srow   = tid;                       // slot row staged
    const float* csrc = nullptr;
    if (cstage) {
        int n = srow >> 4, p = srow & 15;
        int rr = nbr_r[n] * DC_ + (p >> 2);
        int cc = nbr_c[n] * DC_ + (p & 3);
        csrc = F1b + ((size_t)rr * WF_ + cc) * KF_;
    }
    const bool qstage = (tid < 128);
    const int  qp = tid >> 3;                      // 0..15
    const int  qk = (tid * 2) & 15;                // even
    const float* qsrc = qstage
        ? QB + (((qp >> 2) * WF_) + (qp & 3)) * KF_ + qk : nullptr;

    float4 rc0, rc1, rc2, rc3; float2 rq;
    if (cstage) {
        rc0 = *(const float4*)(csrc);
        rc1 = *(const float4*)(csrc + 4);
        rc2 = *(const float4*)(csrc + 8);
        rc3 = *(const float4*)(csrc + 12);
    }
    if (qstage) rq = *(const float2*)(qsrc);

    const int qg  = tid / 36;       // 0..3 for tid<144
    const int cgi = tid % 36;

    float acc[4][4];
#pragma unroll
    for (int r = 0; r < 4; r++)
#pragma unroll
        for (int j = 0; j < 4; j++) acc[r][j] = 0.f;

    for (int ch = 0; ch < 16; ch++) {
        const int bw = ch & 1;
        if (cstage) {
            c_c[bw][0][srow]  = rc0.x; c_c[bw][1][srow]  = rc0.y;
            c_c[bw][2][srow]  = rc0.z; c_c[bw][3][srow]  = rc0.w;
            c_c[bw][4][srow]  = rc1.x; c_c[bw][5][srow]  = rc1.y;
            c_c[bw][6][srow]  = rc1.z; c_c[bw][7][srow]  = rc1.w;
            c_c[bw][8][srow]  = rc2.x; c_c[bw][9][srow]  = rc2.y;
            c_c[bw][10][srow] = rc2.z; c_c[bw][11][srow] = rc2.w;
            c_c[bw][12][srow] = rc3.x; c_c[bw][13][srow] = rc3.y;
            c_c[bw][14][srow] = rc3.z; c_c[bw][15][srow] = rc3.w;
        }
        if (qstage) {
            q_c[bw][qk][qp]     = rq.x;
            q_c[bw][qk + 1][qp] = rq.y;
        }
        if (ch + 1 < 16) {
            const int k0 = (ch + 1) * 16;
            if (cstage) {
                rc0 = *(const float4*)(csrc + k0);
                rc1 = *(const float4*)(csrc + k0 + 4);
                rc2 = *(const float4*)(csrc + k0 + 8);
                rc3 = *(const float4*)(csrc + k0 + 12);
            }
            if (qstage) rq = *(const float2*)(qsrc + k0);
        }
        __syncthreads();
        if (tid < 144) {
#pragma unroll
            for (int kl = 0; kl < 16; kl++) {
                float4 qv = *(const float4*)&q_c[bw][kl][qg * 4];
                float4 cv = *(const float4*)&c_c[bw][kl][cgi * 4];
                float qr[4] = { qv.x, qv.y, qv.z, qv.w };
                float cr[4] = { cv.x, cv.y, cv.z, cv.w };
#pragma unroll
                for (int r = 0; r < 4; r++)
#pragma unroll
                    for (int j = 0; j < 4; j++)
                        acc[r][j] = fmaf(qr[r], cr[j], acc[r][j]);
            }
        }
    }

    if (tid < 144) {
#pragma unroll
        for (int r = 0; r < 4; r++) {
            float bv = 3.402823466e38f; int bi = 0;
#pragma unroll
            for (int j = 0; j < 4; j++) {
                int slot = cgi * 4 + j;
                int n = slot >> 4, p = slot & 15;
                int rr = nbr_r[n] * DC_ + (p >> 2);
                int cc = nbr_c[n] * DC_ + (p & 3);
                float fn = fnb[rr * WF_ + cc];
                float s = fn - 2.f * acc[r][j];
                if (s < bv || (s == bv && slot < bi)) { bv = s; bi = slot; }
            }
            red_v[qg * 4 + r][cgi] = bv;
            red_i[qg * 4 + r][cgi] = bi;
        }
    }
    __syncthreads();
    if (tid < 16) {
        float bv = red_v[tid][0]; int bi = red_i[tid][0];
        for (int t = 1; t < 36; t++) {
            float v = red_v[tid][t]; int i2 = red_i[tid][t];
            if (v < bv || (v == bv && i2 < bi)) { bv = v; bi = i2; }
        }
        int n = bi >> 4, p = bi & 15;
        int rr = nbr_r[n] * DC_ + (p >> 2);
        int cc = nbr_c[n] * DC_ + (p & 3);
        int R = ci * DC_ + (tid >> 2);
        int C = cj * DC_ + (tid & 3);
        float* o = out + (((size_t)(b * HF_ + R) * WF_) + C) * 2;
        o[0] = (float)rr; o[1] = (float)cc;
    }
}

// ---------------------------------------------------------------------------
extern "C" void kernel_launch(void* const* d_in, const int* in_sizes, int n_in,
                              void* d_out, int out_size) {
    int idx[16];
    int m = n_in < 16 ? n_in : 16;
    for (int i = 0; i < m; i++) idx[i] = i;
    for (int i = 1; i < m; i++) {
        int key = idx[i];
        long long ks = in_sizes[key];
        int j = i - 1;
        while (j >= 0 && (long long)in_sizes[idx[j]] > ks) {
            idx[j + 1] = idx[j]; j--;
        }
        idx[j + 1] = key;
    }
    if (m < 4) return;
    const float* g1c = (const float*)d_in[idx[0]];      // F_g1_coarse
    const float* gkc = (const float*)d_in[idx[1]];      // F_gk_coarse
    const float* g1f = (const float*)d_in[idx[m - 2]];  // F_g1_fine
    const float* gkf = (const float*)d_in[idx[m - 1]];  // F_gk_fine
    float* out = (float*)d_out;

    norms_kernel<<<(B_ * HC_ * WC_ + B_ * HF_ * WF_) / 8, 256>>>(g1c, g1f);

    dim3 gc(HC_ * WC_ / 32, B_, 8);
    coarse_kernel<<<gc, 128>>>(g1c, gkc);

    merge_kernel<<<(B_ * HC_ * WC_ + 255) / 256, 256>>>(out);

    dim3 gf(WC_, HC_, B_);
    fine_kernel<<<gf, 160>>>(g1f, gkf, out + B_ * HC_ * WC_ * 2);
}